// round 2
// baseline (speedup 1.0000x reference)
#include <cuda_runtime.h>
#include <cstdint>

// TemporalPyramidPooling: overlapping masked window means at w=4/8/16, stride w/2.
// Hierarchical non-overlapping pair sums -> each output = adjacent-pair sum * (1/count).
//
// Shapes (fixed by the problem):
//   x    [B=8, T=4096, D=512] f32
//   mask [B, T]  (bool; stored as either 1-byte or int32 0/1 -- detected at runtime)
// Outputs concatenated as f32 in reference tuple order:
//   vis4 [B,2047,D], vis8 [B,1023,D], vis16 [B,511,D],
//   msk4 [B,2047],   msk8 [B,1023],   msk16 [B,511]   (valid>0 as 1.0/0.0)

namespace {
constexpr int B   = 8;
constexpr int T   = 4096;
constexpr int D   = 512;
constexpr int S4  = 2047;   // len(arange(0, T-4+1, 2))
constexpr int S8  = 1023;   // len(arange(0, T-8+1, 4))
constexpr int S16 = 511;    // len(arange(0, T-16+1, 8))
constexpr int NGROUPS = T / 8;              // 512 pair8 groups per batch
constexpr int GPB = 16;                     // groups per block (tile = 128 t)
constexpr int BLOCKS_PER_B = NGROUPS / GPB; // 32
}

// 1/max(count, 1e-6) for integer counts 0..16 (count==0 -> num==0, product 0 anyway)
__constant__ float c_inv[17] = {
    1e6f, 1.0f, 0.5f, 1.0f/3.0f, 0.25f, 0.2f, 1.0f/6.0f, 1.0f/7.0f,
    0.125f, 1.0f/9.0f, 0.1f, 1.0f/11.0f, 1.0f/12.0f, 1.0f/13.0f,
    1.0f/14.0f, 1.0f/15.0f, 0.0625f
};

__global__ void __launch_bounds__(512)
tpp_kernel(const float* __restrict__ x,
           const void* __restrict__ mask_raw,
           float* __restrict__ out)
{
    const int blk = blockIdx.x;                 // 0..255
    const int b   = blk / BLOCKS_PER_B;
    const int g0  = (blk % BLOCKS_PER_B) * GPB; // first owned pair8 group
    const int d   = threadIdx.x;                // 0..511, one feature per thread

    // ---- mask storage-layout detection (byte vs int32) ----
    // If mask is uint8 0/1, its int32 view contains words like 0x01010101 (>1).
    // If mask is int32 0/1, every word is exactly 0 or 1.
    __shared__ int s_is_byte;
    if (threadIdx.x < 32) {
        unsigned w = ((const unsigned*)mask_raw)[threadIdx.x];
        int bad = (w > 1u) ? 1 : 0;
        bad = __any_sync(0xffffffffu, bad);
        if (threadIdx.x == 0) s_is_byte = bad;
    }
    __syncthreads();
    const bool mask_is_byte = (s_is_byte != 0);

    const float* xb = x + (size_t)b * T * D + d;

    float* const vis4  = out;
    float* const vis8  = vis4  + (size_t)B * S4  * D;
    float* const vis16 = vis8  + (size_t)B * S8  * D;
    float* const msk4  = vis16 + (size_t)B * S16 * D;
    float* const msk8  = msk4  + B * S4;
    float* const msk16 = msk8  + B * S8;

    const int gEnd  = g0 + GPB;
    const int gLast = (gEnd < NGROUPS) ? gEnd : (gEnd - 1); // inclusive (halo group if it exists)

    // carried from previous group (pair2 last, pair4 last, pair8) + integer counts
    float prev_c3 = 0.f, prev_d1 = 0.f, prev_e = 0.f;
    int   prev_n3 = 0,   prev_m1 = 0,   prev_q = 0;

    for (int g = g0; g <= gLast; ++g) {
        const int t0 = g * 8;

        int mi[8];
        if (mask_is_byte) {
            const uint8_t* mb = (const uint8_t*)mask_raw + (size_t)b * T + t0;
            const uint64_t mw = *reinterpret_cast<const uint64_t*>(mb);
            #pragma unroll
            for (int i = 0; i < 8; ++i) mi[i] = (int)((mw >> (8 * i)) & 1u);
        } else {
            const int4* mw = reinterpret_cast<const int4*>(
                (const int*)mask_raw + (size_t)b * T + t0);
            int4 a = mw[0], c = mw[1];
            mi[0] = (a.x != 0); mi[1] = (a.y != 0); mi[2] = (a.z != 0); mi[3] = (a.w != 0);
            mi[4] = (c.x != 0); mi[5] = (c.y != 0); mi[6] = (c.z != 0); mi[7] = (c.w != 0);
        }

        float v[8];
        const float* xp = xb + (size_t)t0 * D;
        #pragma unroll
        for (int i = 0; i < 8; ++i) {
            float xv = xp[(size_t)i * D];
            v[i] = mi[i] ? xv : 0.0f;
        }

        // hierarchical non-overlapping sums
        const float c0 = v[0] + v[1], c1 = v[2] + v[3],
                    c2 = v[4] + v[5], c3 = v[6] + v[7];
        const int   n0 = mi[0] + mi[1], n1 = mi[2] + mi[3],
                    n2 = mi[4] + mi[5], n3 = mi[6] + mi[7];
        const float d0 = c0 + c1, d1 = c2 + c3;
        const int   m0 = n0 + n1, m1 = n2 + n3;
        const float e  = d0 + d1;
        const int   q  = m0 + m1;

        const bool inTile   = (g < gEnd);
        const bool notFirst = (g > g0);

        if (notFirst) {
            // cross-boundary outputs, owned by this block
            {   // win4 at s = 4g-1
                const int s = 4 * g - 1;
                const int cnt = prev_n3 + n0;
                vis4[((size_t)(b * S4 + s)) * D + d] = (prev_c3 + c0) * c_inv[cnt];
                if (d == 0) msk4[b * S4 + s] = (cnt > 0) ? 1.0f : 0.0f;
            }
            {   // win8 at h = 2g-1
                const int h = 2 * g - 1;
                const int cnt = prev_m1 + m0;
                vis8[((size_t)(b * S8 + h)) * D + d] = (prev_d1 + d0) * c_inv[cnt];
                if (d == 0) msk8[b * S8 + h] = (cnt > 0) ? 1.0f : 0.0f;
            }
            {   // win16 at g-1
                const int cnt = prev_q + q;
                vis16[((size_t)(b * S16 + (g - 1))) * D + d] = (prev_e + e) * c_inv[cnt];
                if (d == 0) msk16[b * S16 + (g - 1)] = (cnt > 0) ? 1.0f : 0.0f;
            }
        }
        if (inTile) {
            const int s = 4 * g;
            int cnt;
            cnt = n0 + n1;
            vis4[((size_t)(b * S4 + s    )) * D + d] = (c0 + c1) * c_inv[cnt];
            if (d == 0) msk4[b * S4 + s    ] = (cnt > 0) ? 1.0f : 0.0f;
            cnt = n1 + n2;
            vis4[((size_t)(b * S4 + s + 1)) * D + d] = (c1 + c2) * c_inv[cnt];
            if (d == 0) msk4[b * S4 + s + 1] = (cnt > 0) ? 1.0f : 0.0f;
            cnt = n2 + n3;
            vis4[((size_t)(b * S4 + s + 2)) * D + d] = (c2 + c3) * c_inv[cnt];
            if (d == 0) msk4[b * S4 + s + 2] = (cnt > 0) ? 1.0f : 0.0f;

            const int h = 2 * g;
            cnt = m0 + m1;
            vis8[((size_t)(b * S8 + h)) * D + d] = (d0 + d1) * c_inv[cnt];
            if (d == 0) msk8[b * S8 + h] = (cnt > 0) ? 1.0f : 0.0f;
        }

        prev_c3 = c3; prev_d1 = d1; prev_e = e;
        prev_n3 = n3; prev_m1 = m1; prev_q = q;
    }
}

extern "C" void kernel_launch(void* const* d_in, const int* in_sizes, int n_in,
                              void* d_out, int out_size)
{
    const float* x    = (const float*)d_in[0];
    const void*  mask = (const void*)d_in[1];
    float*       out  = (float*)d_out;

    tpp_kernel<<<B * BLOCKS_PER_B, 512>>>(x, mask, out);
}

// round 3
// speedup vs baseline: 1.0512x; 1.0512x over previous
#include <cuda_runtime.h>
#include <cstdint>

// TemporalPyramidPooling: overlapping masked window means at w=4/8/16, stride w/2.
// Hierarchical non-overlapping pair sums; float4-vectorized over D.
//
//   x    [B=8, T=4096, D=512] f32
//   mask [B, T]  (bool; stored as 1-byte or int32 0/1 -- detected at runtime)
// Outputs concatenated f32:
//   vis4 [B,2047,D], vis8 [B,1023,D], vis16 [B,511,D],
//   msk4 [B,2047],   msk8 [B,1023],   msk16 [B,511]

namespace {
constexpr int B   = 8;
constexpr int T   = 4096;
constexpr int D   = 512;
constexpr int D4  = D / 4;                  // 128 float4 lanes
constexpr int S4  = 2047;
constexpr int S8  = 1023;
constexpr int S16 = 511;
constexpr int NGROUPS = T / 8;              // 512 pair8 groups per batch
constexpr int GPB = 8;                      // groups per block (tile = 64 t)
constexpr int BLOCKS_PER_B = NGROUPS / GPB; // 64
}

// 1/max(count,1e-6) for counts 0..16 (count==0 -> sum==0, product 0 matches ref)
__constant__ float c_inv[17] = {
    1e6f, 1.0f, 0.5f, 1.0f/3.0f, 0.25f, 0.2f, 1.0f/6.0f, 1.0f/7.0f,
    0.125f, 1.0f/9.0f, 0.1f, 1.0f/11.0f, 1.0f/12.0f, 1.0f/13.0f,
    1.0f/14.0f, 1.0f/15.0f, 0.0625f
};

__device__ __forceinline__ float4 f4add(float4 a, float4 b) {
    return make_float4(a.x + b.x, a.y + b.y, a.z + b.z, a.w + b.w);
}
__device__ __forceinline__ float4 f4scale(float4 a, float s) {
    return make_float4(a.x * s, a.y * s, a.z * s, a.w * s);
}
__device__ __forceinline__ float4 f4zero() { return make_float4(0.f, 0.f, 0.f, 0.f); }

__global__ void __launch_bounds__(D4)
tpp_kernel(const float4* __restrict__ x,
           const void* __restrict__ mask_raw,
           float* __restrict__ out)
{
    const int blk = blockIdx.x;                 // 0..511
    const int b   = blk / BLOCKS_PER_B;
    const int g0  = (blk % BLOCKS_PER_B) * GPB; // first owned pair8 group
    const int d4  = threadIdx.x;                // 0..127

    // ---- mask storage-layout detection (byte vs int32) ----
    __shared__ int s_is_byte;
    if (threadIdx.x < 32) {
        unsigned w = ((const unsigned*)mask_raw)[threadIdx.x];
        int bad = __any_sync(0xffffffffu, (w > 1u) ? 1 : 0);
        if (threadIdx.x == 0) s_is_byte = bad;
    }
    __syncthreads();
    const bool mask_is_byte = (s_is_byte != 0);

    const float4* xb = x + (size_t)b * T * D4 + d4;

    float4* const vis4  = (float4*)out;
    float4* const vis8  = vis4  + (size_t)B * S4  * D4;
    float4* const vis16 = vis8  + (size_t)B * S8  * D4;
    float*  const msk4  = out + (size_t)B * (S4 + S8 + S16) * D;
    float*  const msk8  = msk4 + B * S4;
    float*  const msk16 = msk8 + B * S8;

    const int gEnd  = g0 + GPB;
    const int gLast = (gEnd < NGROUPS) ? gEnd : (gEnd - 1); // halo group if it exists

    float4 prev_c3 = f4zero(), prev_d1 = f4zero(), prev_e = f4zero();
    int    prev_n3 = 0,        prev_m1 = 0,        prev_q = 0;

    for (int g = g0; g <= gLast; ++g) {
        const int t0 = g * 8;

        int mi[8];
        if (mask_is_byte) {
            const uint8_t* mb = (const uint8_t*)mask_raw + (size_t)b * T + t0;
            const uint64_t mw = *reinterpret_cast<const uint64_t*>(mb);
            #pragma unroll
            for (int i = 0; i < 8; ++i) mi[i] = (int)((mw >> (8 * i)) & 1u);
        } else {
            const int4* mw = reinterpret_cast<const int4*>(
                (const int*)mask_raw + (size_t)b * T + t0);
            int4 a = mw[0], c = mw[1];
            mi[0] = (a.x != 0); mi[1] = (a.y != 0); mi[2] = (a.z != 0); mi[3] = (a.w != 0);
            mi[4] = (c.x != 0); mi[5] = (c.y != 0); mi[6] = (c.z != 0); mi[7] = (c.w != 0);
        }

        // 8 independent 16B loads, then mask
        float4 v[8];
        const float4* xp = xb + (size_t)t0 * D4;
        #pragma unroll
        for (int i = 0; i < 8; ++i) v[i] = xp[(size_t)i * D4];
        #pragma unroll
        for (int i = 0; i < 8; ++i) if (!mi[i]) v[i] = f4zero();

        // hierarchical non-overlapping sums
        const float4 c0 = f4add(v[0], v[1]), c1 = f4add(v[2], v[3]),
                     c2 = f4add(v[4], v[5]), c3 = f4add(v[6], v[7]);
        const int    n0 = mi[0] + mi[1], n1 = mi[2] + mi[3],
                     n2 = mi[4] + mi[5], n3 = mi[6] + mi[7];
        const float4 dd0 = f4add(c0, c1), dd1 = f4add(c2, c3);
        const int    m0 = n0 + n1, m1 = n2 + n3;
        const float4 e  = f4add(dd0, dd1);
        const int    q  = m0 + m1;

        const bool inTile   = (g < gEnd);
        const bool notFirst = (g > g0);

        if (notFirst) {
            {   // win4 at s = 4g-1 (crosses group boundary)
                const int s = 4 * g - 1;
                const int cnt = prev_n3 + n0;
                vis4[(size_t)(b * S4 + s) * D4 + d4] = f4scale(f4add(prev_c3, c0), c_inv[cnt]);
                if (d4 == 0) msk4[b * S4 + s] = (cnt > 0) ? 1.0f : 0.0f;
            }
            {   // win8 at h = 2g-1
                const int h = 2 * g - 1;
                const int cnt = prev_m1 + m0;
                vis8[(size_t)(b * S8 + h) * D4 + d4] = f4scale(f4add(prev_d1, dd0), c_inv[cnt]);
                if (d4 == 0) msk8[b * S8 + h] = (cnt > 0) ? 1.0f : 0.0f;
            }
            {   // win16 at g-1
                const int cnt = prev_q + q;
                vis16[(size_t)(b * S16 + (g - 1)) * D4 + d4] = f4scale(f4add(prev_e, e), c_inv[cnt]);
                if (d4 == 0) msk16[b * S16 + (g - 1)] = (cnt > 0) ? 1.0f : 0.0f;
            }
        }
        if (inTile) {
            const int s = 4 * g;
            int cnt;
            cnt = n0 + n1;
            vis4[(size_t)(b * S4 + s    ) * D4 + d4] = f4scale(f4add(c0, c1), c_inv[cnt]);
            if (d4 == 0) msk4[b * S4 + s    ] = (cnt > 0) ? 1.0f : 0.0f;
            cnt = n1 + n2;
            vis4[(size_t)(b * S4 + s + 1) * D4 + d4] = f4scale(f4add(c1, c2), c_inv[cnt]);
            if (d4 == 0) msk4[b * S4 + s + 1] = (cnt > 0) ? 1.0f : 0.0f;
            cnt = n2 + n3;
            vis4[(size_t)(b * S4 + s + 2) * D4 + d4] = f4scale(f4add(c2, c3), c_inv[cnt]);
            if (d4 == 0) msk4[b * S4 + s + 2] = (cnt > 0) ? 1.0f : 0.0f;

            const int h = 2 * g;
            cnt = m0 + m1;
            vis8[(size_t)(b * S8 + h) * D4 + d4] = f4scale(f4add(dd0, dd1), c_inv[cnt]);
            if (d4 == 0) msk8[b * S8 + h] = (cnt > 0) ? 1.0f : 0.0f;
        }

        prev_c3 = c3; prev_d1 = dd1; prev_e = e;
        prev_n3 = n3; prev_m1 = m1;  prev_q = q;
    }
}

extern "C" void kernel_launch(void* const* d_in, const int* in_sizes, int n_in,
                              void* d_out, int out_size)
{
    const float4* x    = (const float4*)d_in[0];
    const void*   mask = (const void*)d_in[1];
    float*        out  = (float*)d_out;

    tpp_kernel<<<B * BLOCKS_PER_B, D4>>>(x, mask, out);
}

// round 4
// speedup vs baseline: 1.4146x; 1.3457x over previous
#include <cuda_runtime.h>
#include <cstdint>

// TemporalPyramidPooling: overlapping masked window means at w=4/8/16, stride w/2.
// Hierarchical non-overlapping pair sums; float4-vectorized over D.
// R4: GPB=4 (1024 CTAs -> ~41% occupancy) + fully-unrolled main loop + halo epilogue.
//
//   x    [B=8, T=4096, D=512] f32
//   mask [B, T]  (bool; stored as 1-byte or int32 0/1 -- detected at runtime)
// Outputs concatenated f32:
//   vis4 [B,2047,D], vis8 [B,1023,D], vis16 [B,511,D],
//   msk4 [B,2047],   msk8 [B,1023],   msk16 [B,511]

namespace {
constexpr int B   = 8;
constexpr int T   = 4096;
constexpr int D   = 512;
constexpr int D4  = D / 4;                  // 128 float4 lanes
constexpr int S4  = 2047;
constexpr int S8  = 1023;
constexpr int S16 = 511;
constexpr int NGROUPS = T / 8;              // 512 pair8 groups per batch
constexpr int GPB = 4;                      // groups per block (tile = 32 t)
constexpr int BLOCKS_PER_B = NGROUPS / GPB; // 128
}

// 1/max(count,1e-6) for counts 0..16 (count==0 -> sum==0, product 0 matches ref)
__constant__ float c_inv[17] = {
    1e6f, 1.0f, 0.5f, 1.0f/3.0f, 0.25f, 0.2f, 1.0f/6.0f, 1.0f/7.0f,
    0.125f, 1.0f/9.0f, 0.1f, 1.0f/11.0f, 1.0f/12.0f, 1.0f/13.0f,
    1.0f/14.0f, 1.0f/15.0f, 0.0625f
};

__device__ __forceinline__ float4 f4add(float4 a, float4 b) {
    return make_float4(a.x + b.x, a.y + b.y, a.z + b.z, a.w + b.w);
}
__device__ __forceinline__ float4 f4scale(float4 a, float s) {
    return make_float4(a.x * s, a.y * s, a.z * s, a.w * s);
}
__device__ __forceinline__ float4 f4zero() { return make_float4(0.f, 0.f, 0.f, 0.f); }

struct GroupSums {
    float4 c0, c1, c2, c3;   // pair2 sums
    float4 d0, d1;           // pair4 sums
    float4 e;                // pair8 sum
    int n0, n1, n2, n3, m0, m1, q;
};

// Load + mask + hierarchical-sum one pair8 group.
__device__ __forceinline__ GroupSums load_group(
    const float4* __restrict__ xb, const void* __restrict__ mask_raw,
    bool mask_is_byte, int b, int g, int d4)
{
    const int t0 = g * 8;
    int mi[8];
    if (mask_is_byte) {
        const uint8_t* mb = (const uint8_t*)mask_raw + (size_t)b * T + t0;
        const uint64_t mw = *reinterpret_cast<const uint64_t*>(mb);
        #pragma unroll
        for (int i = 0; i < 8; ++i) mi[i] = (int)((mw >> (8 * i)) & 1u);
    } else {
        const int4* mw = reinterpret_cast<const int4*>(
            (const int*)mask_raw + (size_t)b * T + t0);
        int4 a = mw[0], c = mw[1];
        mi[0] = (a.x != 0); mi[1] = (a.y != 0); mi[2] = (a.z != 0); mi[3] = (a.w != 0);
        mi[4] = (c.x != 0); mi[5] = (c.y != 0); mi[6] = (c.z != 0); mi[7] = (c.w != 0);
    }

    float4 v[8];
    const float4* xp = xb + (size_t)t0 * D4;
    #pragma unroll
    for (int i = 0; i < 8; ++i) v[i] = xp[(size_t)i * D4];
    #pragma unroll
    for (int i = 0; i < 8; ++i) if (!mi[i]) v[i] = f4zero();

    GroupSums s;
    s.c0 = f4add(v[0], v[1]); s.c1 = f4add(v[2], v[3]);
    s.c2 = f4add(v[4], v[5]); s.c3 = f4add(v[6], v[7]);
    s.n0 = mi[0] + mi[1]; s.n1 = mi[2] + mi[3];
    s.n2 = mi[4] + mi[5]; s.n3 = mi[6] + mi[7];
    s.d0 = f4add(s.c0, s.c1); s.d1 = f4add(s.c2, s.c3);
    s.m0 = s.n0 + s.n1; s.m1 = s.n2 + s.n3;
    s.e  = f4add(s.d0, s.d1);
    s.q  = s.m0 + s.m1;
    return s;
}

__global__ void __launch_bounds__(D4, 8)
tpp_kernel(const float4* __restrict__ x,
           const void* __restrict__ mask_raw,
           float* __restrict__ out)
{
    const int blk = blockIdx.x;                 // 0..1023
    const int b   = blk / BLOCKS_PER_B;
    const int g0  = (blk % BLOCKS_PER_B) * GPB; // first owned pair8 group
    const int d4  = threadIdx.x;                // 0..127

    // ---- mask storage-layout detection (byte vs int32) ----
    __shared__ int s_is_byte;
    if (threadIdx.x < 32) {
        unsigned w = ((const unsigned*)mask_raw)[threadIdx.x];
        int bad = __any_sync(0xffffffffu, (w > 1u) ? 1 : 0);
        if (threadIdx.x == 0) s_is_byte = bad;
    }
    __syncthreads();
    const bool mask_is_byte = (s_is_byte != 0);

    const float4* xb = x + (size_t)b * T * D4 + d4;

    float4* const vis4  = (float4*)out;
    float4* const vis8  = vis4  + (size_t)B * S4  * D4;
    float4* const vis16 = vis8  + (size_t)B * S8  * D4;
    float*  const msk4  = out + (size_t)B * (S4 + S8 + S16) * D;
    float*  const msk8  = msk4 + B * S4;
    float*  const msk16 = msk8 + B * S8;

    float4 prev_c3 = f4zero(), prev_d1 = f4zero(), prev_e = f4zero();
    int    prev_n3 = 0,        prev_m1 = 0,        prev_q = 0;

    #pragma unroll
    for (int k = 0; k < GPB; ++k) {
        const int g = g0 + k;
        const GroupSums s = load_group(xb, mask_raw, mask_is_byte, b, g, d4);

        if (k > 0) {
            {   // win4 at 4g-1 (crosses group boundary)
                const int si = 4 * g - 1;
                const int cnt = prev_n3 + s.n0;
                vis4[(size_t)(b * S4 + si) * D4 + d4] = f4scale(f4add(prev_c3, s.c0), c_inv[cnt]);
                if (d4 == 0) msk4[b * S4 + si] = (cnt > 0) ? 1.0f : 0.0f;
            }
            {   // win8 at 2g-1
                const int h = 2 * g - 1;
                const int cnt = prev_m1 + s.m0;
                vis8[(size_t)(b * S8 + h) * D4 + d4] = f4scale(f4add(prev_d1, s.d0), c_inv[cnt]);
                if (d4 == 0) msk8[b * S8 + h] = (cnt > 0) ? 1.0f : 0.0f;
            }
            {   // win16 at g-1
                const int cnt = prev_q + s.q;
                vis16[(size_t)(b * S16 + (g - 1)) * D4 + d4] = f4scale(f4add(prev_e, s.e), c_inv[cnt]);
                if (d4 == 0) msk16[b * S16 + (g - 1)] = (cnt > 0) ? 1.0f : 0.0f;
            }
        }
        {   // in-tile outputs
            const int si = 4 * g;
            int cnt;
            cnt = s.n0 + s.n1;
            vis4[(size_t)(b * S4 + si    ) * D4 + d4] = f4scale(f4add(s.c0, s.c1), c_inv[cnt]);
            if (d4 == 0) msk4[b * S4 + si    ] = (cnt > 0) ? 1.0f : 0.0f;
            cnt = s.n1 + s.n2;
            vis4[(size_t)(b * S4 + si + 1) * D4 + d4] = f4scale(f4add(s.c1, s.c2), c_inv[cnt]);
            if (d4 == 0) msk4[b * S4 + si + 1] = (cnt > 0) ? 1.0f : 0.0f;
            cnt = s.n2 + s.n3;
            vis4[(size_t)(b * S4 + si + 2) * D4 + d4] = f4scale(f4add(s.c2, s.c3), c_inv[cnt]);
            if (d4 == 0) msk4[b * S4 + si + 2] = (cnt > 0) ? 1.0f : 0.0f;

            const int h = 2 * g;
            cnt = s.m0 + s.m1;
            vis8[(size_t)(b * S8 + h) * D4 + d4] = f4scale(f4add(s.d0, s.d1), c_inv[cnt]);
            if (d4 == 0) msk8[b * S8 + h] = (cnt > 0) ? 1.0f : 0.0f;
        }

        prev_c3 = s.c3; prev_d1 = s.d1; prev_e = s.e;
        prev_n3 = s.n3; prev_m1 = s.m1; prev_q = s.q;
    }

    // ---- halo epilogue: boundary windows into group gEnd (owned by this block) ----
    const int gEnd = g0 + GPB;
    if (gEnd < NGROUPS) {
        const GroupSums s = load_group(xb, mask_raw, mask_is_byte, b, gEnd, d4);
        {   // win4 at 4*gEnd-1
            const int si = 4 * gEnd - 1;
            const int cnt = prev_n3 + s.n0;
            vis4[(size_t)(b * S4 + si) * D4 + d4] = f4scale(f4add(prev_c3, s.c0), c_inv[cnt]);
            if (d4 == 0) msk4[b * S4 + si] = (cnt > 0) ? 1.0f : 0.0f;
        }
        {   // win8 at 2*gEnd-1
            const int h = 2 * gEnd - 1;
            const int cnt = prev_m1 + s.m0;
            vis8[(size_t)(b * S8 + h) * D4 + d4] = f4scale(f4add(prev_d1, s.d0), c_inv[cnt]);
            if (d4 == 0) msk8[b * S8 + h] = (cnt > 0) ? 1.0f : 0.0f;
        }
        {   // win16 at gEnd-1
            const int cnt = prev_q + s.q;
            vis16[(size_t)(b * S16 + (gEnd - 1)) * D4 + d4] = f4scale(f4add(prev_e, s.e), c_inv[cnt]);
            if (d4 == 0) msk16[b * S16 + (gEnd - 1)] = (cnt > 0) ? 1.0f : 0.0f;
        }
    }
}

extern "C" void kernel_launch(void* const* d_in, const int* in_sizes, int n_in,
                              void* d_out, int out_size)
{
    const float4* x    = (const float4*)d_in[0];
    const void*   mask = (const void*)d_in[1];
    float*        out  = (float*)d_out;

    tpp_kernel<<<B * BLOCKS_PER_B, D4>>>(x, mask, out);
}

// round 5
// speedup vs baseline: 1.4264x; 1.0083x over previous
#include <cuda_runtime.h>
#include <cstdint>

// TemporalPyramidPooling: overlapping masked window means at w=4/8/16, stride w/2.
// Hierarchical non-overlapping pair sums; float4-vectorized over D.
// R5: GPB=2 (2048 CTAs -> reg-capped 8 CTA/SM residency, ~50% occ); halo reads hit L2
//     (whole x fits in 126MB L2), so extra reads don't cost DRAM bytes.
//
//   x    [B=8, T=4096, D=512] f32
//   mask [B, T]  (bool; stored as 1-byte or int32 0/1 -- detected at runtime)
// Outputs concatenated f32:
//   vis4 [B,2047,D], vis8 [B,1023,D], vis16 [B,511,D],
//   msk4 [B,2047],   msk8 [B,1023],   msk16 [B,511]

namespace {
constexpr int B   = 8;
constexpr int T   = 4096;
constexpr int D   = 512;
constexpr int D4  = D / 4;                  // 128 float4 lanes
constexpr int S4  = 2047;
constexpr int S8  = 1023;
constexpr int S16 = 511;
constexpr int NGROUPS = T / 8;              // 512 pair8 groups per batch
constexpr int GPB = 2;                      // groups per block (tile = 16 t)
constexpr int BLOCKS_PER_B = NGROUPS / GPB; // 256
}

// 1/max(count,1e-6) for counts 0..16 (count==0 -> sum==0, product 0 matches ref)
__constant__ float c_inv[17] = {
    1e6f, 1.0f, 0.5f, 1.0f/3.0f, 0.25f, 0.2f, 1.0f/6.0f, 1.0f/7.0f,
    0.125f, 1.0f/9.0f, 0.1f, 1.0f/11.0f, 1.0f/12.0f, 1.0f/13.0f,
    1.0f/14.0f, 1.0f/15.0f, 0.0625f
};

__device__ __forceinline__ float4 f4add(float4 a, float4 b) {
    return make_float4(a.x + b.x, a.y + b.y, a.z + b.z, a.w + b.w);
}
__device__ __forceinline__ float4 f4scale(float4 a, float s) {
    return make_float4(a.x * s, a.y * s, a.z * s, a.w * s);
}
__device__ __forceinline__ float4 f4zero() { return make_float4(0.f, 0.f, 0.f, 0.f); }

struct GroupSums {
    float4 c0, c1, c2, c3;   // pair2 sums
    float4 d0, d1;           // pair4 sums
    float4 e;                // pair8 sum
    int n0, n1, n2, n3, m0, m1, q;
};

// Load + mask + hierarchical-sum one pair8 group.
__device__ __forceinline__ GroupSums load_group(
    const float4* __restrict__ xb, const void* __restrict__ mask_raw,
    bool mask_is_byte, int b, int g, int d4)
{
    const int t0 = g * 8;
    int mi[8];
    if (mask_is_byte) {
        const uint8_t* mb = (const uint8_t*)mask_raw + (size_t)b * T + t0;
        const uint64_t mw = *reinterpret_cast<const uint64_t*>(mb);
        #pragma unroll
        for (int i = 0; i < 8; ++i) mi[i] = (int)((mw >> (8 * i)) & 1u);
    } else {
        const int4* mw = reinterpret_cast<const int4*>(
            (const int*)mask_raw + (size_t)b * T + t0);
        int4 a = mw[0], c = mw[1];
        mi[0] = (a.x != 0); mi[1] = (a.y != 0); mi[2] = (a.z != 0); mi[3] = (a.w != 0);
        mi[4] = (c.x != 0); mi[5] = (c.y != 0); mi[6] = (c.z != 0); mi[7] = (c.w != 0);
    }

    float4 v[8];
    const float4* xp = xb + (size_t)t0 * D4;
    #pragma unroll
    for (int i = 0; i < 8; ++i) v[i] = xp[(size_t)i * D4];
    #pragma unroll
    for (int i = 0; i < 8; ++i) if (!mi[i]) v[i] = f4zero();

    GroupSums s;
    s.c0 = f4add(v[0], v[1]); s.c1 = f4add(v[2], v[3]);
    s.c2 = f4add(v[4], v[5]); s.c3 = f4add(v[6], v[7]);
    s.n0 = mi[0] + mi[1]; s.n1 = mi[2] + mi[3];
    s.n2 = mi[4] + mi[5]; s.n3 = mi[6] + mi[7];
    s.d0 = f4add(s.c0, s.c1); s.d1 = f4add(s.c2, s.c3);
    s.m0 = s.n0 + s.n1; s.m1 = s.n2 + s.n3;
    s.e  = f4add(s.d0, s.d1);
    s.q  = s.m0 + s.m1;
    return s;
}

__global__ void __launch_bounds__(D4, 8)
tpp_kernel(const float4* __restrict__ x,
           const void* __restrict__ mask_raw,
           float* __restrict__ out)
{
    const int blk = blockIdx.x;                 // 0..2047
    const int b   = blk / BLOCKS_PER_B;
    const int g0  = (blk % BLOCKS_PER_B) * GPB; // first owned pair8 group
    const int d4  = threadIdx.x;                // 0..127

    // ---- mask storage-layout detection (byte vs int32) ----
    __shared__ int s_is_byte;
    if (threadIdx.x < 32) {
        unsigned w = ((const unsigned*)mask_raw)[threadIdx.x];
        int bad = __any_sync(0xffffffffu, (w > 1u) ? 1 : 0);
        if (threadIdx.x == 0) s_is_byte = bad;
    }
    __syncthreads();
    const bool mask_is_byte = (s_is_byte != 0);

    const float4* xb = x + (size_t)b * T * D4 + d4;

    float4* const vis4  = (float4*)out;
    float4* const vis8  = vis4  + (size_t)B * S4  * D4;
    float4* const vis16 = vis8  + (size_t)B * S8  * D4;
    float*  const msk4  = out + (size_t)B * (S4 + S8 + S16) * D;
    float*  const msk8  = msk4 + B * S4;
    float*  const msk16 = msk8 + B * S8;

    float4 prev_c3 = f4zero(), prev_d1 = f4zero(), prev_e = f4zero();
    int    prev_n3 = 0,        prev_m1 = 0,        prev_q = 0;

    #pragma unroll
    for (int k = 0; k < GPB; ++k) {
        const int g = g0 + k;
        const GroupSums s = load_group(xb, mask_raw, mask_is_byte, b, g, d4);

        if (k > 0) {
            {   // win4 at 4g-1 (crosses group boundary)
                const int si = 4 * g - 1;
                const int cnt = prev_n3 + s.n0;
                vis4[(size_t)(b * S4 + si) * D4 + d4] = f4scale(f4add(prev_c3, s.c0), c_inv[cnt]);
                if (d4 == 0) msk4[b * S4 + si] = (cnt > 0) ? 1.0f : 0.0f;
            }
            {   // win8 at 2g-1
                const int h = 2 * g - 1;
                const int cnt = prev_m1 + s.m0;
                vis8[(size_t)(b * S8 + h) * D4 + d4] = f4scale(f4add(prev_d1, s.d0), c_inv[cnt]);
                if (d4 == 0) msk8[b * S8 + h] = (cnt > 0) ? 1.0f : 0.0f;
            }
            {   // win16 at g-1
                const int cnt = prev_q + s.q;
                vis16[(size_t)(b * S16 + (g - 1)) * D4 + d4] = f4scale(f4add(prev_e, s.e), c_inv[cnt]);
                if (d4 == 0) msk16[b * S16 + (g - 1)] = (cnt > 0) ? 1.0f : 0.0f;
            }
        }
        {   // in-tile outputs
            const int si = 4 * g;
            int cnt;
            cnt = s.n0 + s.n1;
            vis4[(size_t)(b * S4 + si    ) * D4 + d4] = f4scale(f4add(s.c0, s.c1), c_inv[cnt]);
            if (d4 == 0) msk4[b * S4 + si    ] = (cnt > 0) ? 1.0f : 0.0f;
            cnt = s.n1 + s.n2;
            vis4[(size_t)(b * S4 + si + 1) * D4 + d4] = f4scale(f4add(s.c1, s.c2), c_inv[cnt]);
            if (d4 == 0) msk4[b * S4 + si + 1] = (cnt > 0) ? 1.0f : 0.0f;
            cnt = s.n2 + s.n3;
            vis4[(size_t)(b * S4 + si + 2) * D4 + d4] = f4scale(f4add(s.c2, s.c3), c_inv[cnt]);
            if (d4 == 0) msk4[b * S4 + si + 2] = (cnt > 0) ? 1.0f : 0.0f;

            const int h = 2 * g;
            cnt = s.m0 + s.m1;
            vis8[(size_t)(b * S8 + h) * D4 + d4] = f4scale(f4add(s.d0, s.d1), c_inv[cnt]);
            if (d4 == 0) msk8[b * S8 + h] = (cnt > 0) ? 1.0f : 0.0f;
        }

        prev_c3 = s.c3; prev_d1 = s.d1; prev_e = s.e;
        prev_n3 = s.n3; prev_m1 = s.m1; prev_q = s.q;
    }

    // ---- halo epilogue: boundary windows into group gEnd (owned by this block) ----
    const int gEnd = g0 + GPB;
    if (gEnd < NGROUPS) {
        const GroupSums s = load_group(xb, mask_raw, mask_is_byte, b, gEnd, d4);
        {   // win4 at 4*gEnd-1
            const int si = 4 * gEnd - 1;
            const int cnt = prev_n3 + s.n0;
            vis4[(size_t)(b * S4 + si) * D4 + d4] = f4scale(f4add(prev_c3, s.c0), c_inv[cnt]);
            if (d4 == 0) msk4[b * S4 + si] = (cnt > 0) ? 1.0f : 0.0f;
        }
        {   // win8 at 2*gEnd-1
            const int h = 2 * gEnd - 1;
            const int cnt = prev_m1 + s.m0;
            vis8[(size_t)(b * S8 + h) * D4 + d4] = f4scale(f4add(prev_d1, s.d0), c_inv[cnt]);
            if (d4 == 0) msk8[b * S8 + h] = (cnt > 0) ? 1.0f : 0.0f;
        }
        {   // win16 at gEnd-1
            const int cnt = prev_q + s.q;
            vis16[(size_t)(b * S16 + (gEnd - 1)) * D4 + d4] = f4scale(f4add(prev_e, s.e), c_inv[cnt]);
            if (d4 == 0) msk16[b * S16 + (gEnd - 1)] = (cnt > 0) ? 1.0f : 0.0f;
        }
    }
}

extern "C" void kernel_launch(void* const* d_in, const int* in_sizes, int n_in,
                              void* d_out, int out_size)
{
    const float4* x    = (const float4*)d_in[0];
    const void*   mask = (const void*)d_in[1];
    float*        out  = (float*)d_out;

    tpp_kernel<<<B * BLOCKS_PER_B, D4>>>(x, mask, out);
}

// round 6
// speedup vs baseline: 1.5490x; 1.0860x over previous
#include <cuda_runtime.h>
#include <cstdint>

// TemporalPyramidPooling: overlapping masked window means at w=4/8/16, stride w/2.
// Hierarchical non-overlapping pair sums; float4-vectorized over D.
// R6: GPB=4 + explicit 2-stage load pipeline (MLP ~16 LDG.128/warp) + __stcs
//     streaming stores (outputs never re-read; keep x halo resident in L2).
//
//   x    [B=8, T=4096, D=512] f32
//   mask [B, T]  (bool; stored as 1-byte or int32 0/1 -- detected at runtime)
// Outputs concatenated f32:
//   vis4 [B,2047,D], vis8 [B,1023,D], vis16 [B,511,D],
//   msk4 [B,2047],   msk8 [B,1023],   msk16 [B,511]

namespace {
constexpr int B   = 8;
constexpr int T   = 4096;
constexpr int D   = 512;
constexpr int D4  = D / 4;                  // 128 float4 lanes
constexpr int S4  = 2047;
constexpr int S8  = 1023;
constexpr int S16 = 511;
constexpr int NGROUPS = T / 8;              // 512 pair8 groups per batch
constexpr int GPB = 4;                      // groups per block (tile = 32 t)
constexpr int BLOCKS_PER_B = NGROUPS / GPB; // 128
}

// 1/max(count,1e-6) for counts 0..16 (count==0 -> sum==0, product 0 matches ref)
__constant__ float c_inv[17] = {
    1e6f, 1.0f, 0.5f, 1.0f/3.0f, 0.25f, 0.2f, 1.0f/6.0f, 1.0f/7.0f,
    0.125f, 1.0f/9.0f, 0.1f, 1.0f/11.0f, 1.0f/12.0f, 1.0f/13.0f,
    1.0f/14.0f, 1.0f/15.0f, 0.0625f
};

__device__ __forceinline__ float4 f4add(float4 a, float4 b) {
    return make_float4(a.x + b.x, a.y + b.y, a.z + b.z, a.w + b.w);
}
__device__ __forceinline__ float4 f4scale(float4 a, float s) {
    return make_float4(a.x * s, a.y * s, a.z * s, a.w * s);
}
__device__ __forceinline__ float4 f4zero() { return make_float4(0.f, 0.f, 0.f, 0.f); }

// Raw loaded data for one pair8 group: 8 float4 + mask bits (bit i = mask[t0+i]).
struct RawGroup {
    float4  v[8];
    unsigned mbits;
};

struct GroupSums {
    float4 c0, c1, c2, c3;   // pair2 sums
    float4 d0, d1;           // pair4 sums
    float4 e;                // pair8 sum
    int n0, n1, n2, n3, m0, m1, q;
};

// Issue the loads for one group (no dependent compute -- keeps LDGs in flight).
__device__ __forceinline__ RawGroup load_raw(
    const float4* __restrict__ xb, const void* __restrict__ mask_raw,
    bool mask_is_byte, int b, int g)
{
    RawGroup r;
    const int t0 = g * 8;
    if (mask_is_byte) {
        const uint8_t* mb = (const uint8_t*)mask_raw + (size_t)b * T + t0;
        const uint64_t mw = *reinterpret_cast<const uint64_t*>(mb);
        unsigned bits = 0;
        #pragma unroll
        for (int i = 0; i < 8; ++i) bits |= ((unsigned)(mw >> (8 * i)) & 1u) << i;
        r.mbits = bits;
    } else {
        const int4* mw = reinterpret_cast<const int4*>(
            (const int*)mask_raw + (size_t)b * T + t0);
        int4 a = mw[0], c = mw[1];
        r.mbits = (unsigned)((a.x != 0)      | ((a.y != 0) << 1) |
                             ((a.z != 0) << 2) | ((a.w != 0) << 3) |
                             ((c.x != 0) << 4) | ((c.y != 0) << 5) |
                             ((c.z != 0) << 6) | ((c.w != 0) << 7));
    }
    const float4* xp = xb + (size_t)t0 * D4;
    #pragma unroll
    for (int i = 0; i < 8; ++i) r.v[i] = xp[(size_t)i * D4];
    return r;
}

// Mask + hierarchical sums (consumes the loaded registers).
__device__ __forceinline__ GroupSums compute_sums(const RawGroup& r)
{
    float4 v[8];
    int mi[8];
    #pragma unroll
    for (int i = 0; i < 8; ++i) {
        mi[i] = (int)((r.mbits >> i) & 1u);
        v[i]  = mi[i] ? r.v[i] : f4zero();
    }
    GroupSums s;
    s.c0 = f4add(v[0], v[1]); s.c1 = f4add(v[2], v[3]);
    s.c2 = f4add(v[4], v[5]); s.c3 = f4add(v[6], v[7]);
    s.n0 = mi[0] + mi[1]; s.n1 = mi[2] + mi[3];
    s.n2 = mi[4] + mi[5]; s.n3 = mi[6] + mi[7];
    s.d0 = f4add(s.c0, s.c1); s.d1 = f4add(s.c2, s.c3);
    s.m0 = s.n0 + s.n1; s.m1 = s.n2 + s.n3;
    s.e  = f4add(s.d0, s.d1);
    s.q  = s.m0 + s.m1;
    return s;
}

__global__ void __launch_bounds__(D4, 5)
tpp_kernel(const float4* __restrict__ x,
           const void* __restrict__ mask_raw,
           float* __restrict__ out)
{
    const int blk = blockIdx.x;                 // 0..1023
    const int b   = blk / BLOCKS_PER_B;
    const int g0  = (blk % BLOCKS_PER_B) * GPB; // first owned pair8 group
    const int d4  = threadIdx.x;                // 0..127

    // ---- mask storage-layout detection (byte vs int32) ----
    __shared__ int s_is_byte;
    if (threadIdx.x < 32) {
        unsigned w = ((const unsigned*)mask_raw)[threadIdx.x];
        int bad = __any_sync(0xffffffffu, (w > 1u) ? 1 : 0);
        if (threadIdx.x == 0) s_is_byte = bad;
    }
    __syncthreads();
    const bool mask_is_byte = (s_is_byte != 0);

    const float4* xb = x + (size_t)b * T * D4 + d4;

    float4* const vis4  = (float4*)out;
    float4* const vis8  = vis4  + (size_t)B * S4  * D4;
    float4* const vis16 = vis8  + (size_t)B * S8  * D4;
    float*  const msk4  = out + (size_t)B * (S4 + S8 + S16) * D;
    float*  const msk8  = msk4 + B * S4;
    float*  const msk16 = msk8 + B * S8;

    const bool hasHalo = (g0 + GPB) < NGROUPS;

    float4 prev_c3 = f4zero(), prev_d1 = f4zero(), prev_e = f4zero();
    int    prev_n3 = 0,        prev_m1 = 0,        prev_q = 0;

    // ---- 2-stage pipeline: loads of group k+1 issue before stores of group k ----
    RawGroup cur = load_raw(xb, mask_raw, mask_is_byte, b, g0);

    #pragma unroll
    for (int k = 0; k < GPB; ++k) {
        const int g = g0 + k;
        const bool has_next = (k + 1 < GPB) || hasHalo;

        RawGroup nxt;
        if (has_next) nxt = load_raw(xb, mask_raw, mask_is_byte, b, g + 1);

        const GroupSums s = compute_sums(cur);

        if (k > 0) {
            {   // win4 at 4g-1 (crosses group boundary)
                const int si = 4 * g - 1;
                const int cnt = prev_n3 + s.n0;
                __stcs(&vis4[(size_t)(b * S4 + si) * D4 + d4],
                       f4scale(f4add(prev_c3, s.c0), c_inv[cnt]));
                if (d4 == 0) __stcs(&msk4[b * S4 + si], (cnt > 0) ? 1.0f : 0.0f);
            }
            {   // win8 at 2g-1
                const int h = 2 * g - 1;
                const int cnt = prev_m1 + s.m0;
                __stcs(&vis8[(size_t)(b * S8 + h) * D4 + d4],
                       f4scale(f4add(prev_d1, s.d0), c_inv[cnt]));
                if (d4 == 0) __stcs(&msk8[b * S8 + h], (cnt > 0) ? 1.0f : 0.0f);
            }
            {   // win16 at g-1
                const int cnt = prev_q + s.q;
                __stcs(&vis16[(size_t)(b * S16 + (g - 1)) * D4 + d4],
                       f4scale(f4add(prev_e, s.e), c_inv[cnt]));
                if (d4 == 0) __stcs(&msk16[b * S16 + (g - 1)], (cnt > 0) ? 1.0f : 0.0f);
            }
        }
        {   // in-tile outputs
            const int si = 4 * g;
            int cnt;
            cnt = s.n0 + s.n1;
            __stcs(&vis4[(size_t)(b * S4 + si    ) * D4 + d4],
                   f4scale(f4add(s.c0, s.c1), c_inv[cnt]));
            if (d4 == 0) __stcs(&msk4[b * S4 + si    ], (cnt > 0) ? 1.0f : 0.0f);
            cnt = s.n1 + s.n2;
            __stcs(&vis4[(size_t)(b * S4 + si + 1) * D4 + d4],
                   f4scale(f4add(s.c1, s.c2), c_inv[cnt]));
            if (d4 == 0) __stcs(&msk4[b * S4 + si + 1], (cnt > 0) ? 1.0f : 0.0f);
            cnt = s.n2 + s.n3;
            __stcs(&vis4[(size_t)(b * S4 + si + 2) * D4 + d4],
                   f4scale(f4add(s.c2, s.c3), c_inv[cnt]));
            if (d4 == 0) __stcs(&msk4[b * S4 + si + 2], (cnt > 0) ? 1.0f : 0.0f);

            const int h = 2 * g;
            cnt = s.m0 + s.m1;
            __stcs(&vis8[(size_t)(b * S8 + h) * D4 + d4],
                   f4scale(f4add(s.d0, s.d1), c_inv[cnt]));
            if (d4 == 0) __stcs(&msk8[b * S8 + h], (cnt > 0) ? 1.0f : 0.0f);
        }

        prev_c3 = s.c3; prev_d1 = s.d1; prev_e = s.e;
        prev_n3 = s.n3; prev_m1 = s.m1; prev_q = s.q;

        cur = nxt;
    }

    // ---- halo epilogue: boundary windows into group gEnd (cur holds it) ----
    if (hasHalo) {
        const int gEnd = g0 + GPB;
        const GroupSums s = compute_sums(cur);
        {   // win4 at 4*gEnd-1
            const int si = 4 * gEnd - 1;
            const int cnt = prev_n3 + s.n0;
            __stcs(&vis4[(size_t)(b * S4 + si) * D4 + d4],
                   f4scale(f4add(prev_c3, s.c0), c_inv[cnt]));
            if (d4 == 0) __stcs(&msk4[b * S4 + si], (cnt > 0) ? 1.0f : 0.0f);
        }
        {   // win8 at 2*gEnd-1
            const int h = 2 * gEnd - 1;
            const int cnt = prev_m1 + s.m0;
            __stcs(&vis8[(size_t)(b * S8 + h) * D4 + d4],
                   f4scale(f4add(prev_d1, s.d0), c_inv[cnt]));
            if (d4 == 0) __stcs(&msk8[b * S8 + h], (cnt > 0) ? 1.0f : 0.0f);
        }
        {   // win16 at gEnd-1
            const int cnt = prev_q + s.q;
            __stcs(&vis16[(size_t)(b * S16 + (gEnd - 1)) * D4 + d4],
                   f4scale(f4add(prev_e, s.e), c_inv[cnt]));
            if (d4 == 0) __stcs(&msk16[b * S16 + (gEnd - 1)], (cnt > 0) ? 1.0f : 0.0f);
        }
    }
}

extern "C" void kernel_launch(void* const* d_in, const int* in_sizes, int n_in,
                              void* d_out, int out_size)
{
    const float4* x    = (const float4*)d_in[0];
    const void*   mask = (const void*)d_in[1];
    float*        out  = (float*)d_out;

    tpp_kernel<<<B * BLOCKS_PER_B, D4>>>(x, mask, out);
}

// round 7
// speedup vs baseline: 1.7117x; 1.1050x over previous
#include <cuda_runtime.h>
#include <cstdint>

// TemporalPyramidPooling: overlapping masked window means at w=4/8/16, stride w/2.
// Hierarchical non-overlapping pair sums; float4-vectorized over D.
// R7: D-split-2 CTAs (64 threads, each owns half of D4) at GPB=4.
//     -> R5's occupancy (2048 CTAs, 4096 warps) with R4's 25% halo traffic.
//     __launch_bounds__(64,14) keeps regs <=73 so the whole grid is one wave.
//
//   x    [B=8, T=4096, D=512] f32
//   mask [B, T]  (bool; stored as 1-byte or int32 0/1 -- detected at runtime)
// Outputs concatenated f32:
//   vis4 [B,2047,D], vis8 [B,1023,D], vis16 [B,511,D],
//   msk4 [B,2047],   msk8 [B,1023],   msk16 [B,511]

namespace {
constexpr int B   = 8;
constexpr int T   = 4096;
constexpr int D   = 512;
constexpr int D4  = D / 4;                  // 128 float4 lanes
constexpr int S4  = 2047;
constexpr int S8  = 1023;
constexpr int S16 = 511;
constexpr int NGROUPS = T / 8;              // 512 pair8 groups per batch
constexpr int GPB = 4;                      // groups per block (tile = 32 t)
constexpr int BLOCKS_PER_B = NGROUPS / GPB; // 128
constexpr int DSPLIT = 2;                   // CTAs per (b, gtile) along D
constexpr int BLK = D4 / DSPLIT;            // 64 threads
}

// 1/max(count,1e-6) for counts 0..16 (count==0 -> sum==0, product 0 matches ref)
__constant__ float c_inv[17] = {
    1e6f, 1.0f, 0.5f, 1.0f/3.0f, 0.25f, 0.2f, 1.0f/6.0f, 1.0f/7.0f,
    0.125f, 1.0f/9.0f, 0.1f, 1.0f/11.0f, 1.0f/12.0f, 1.0f/13.0f,
    1.0f/14.0f, 1.0f/15.0f, 0.0625f
};

__device__ __forceinline__ float4 f4add(float4 a, float4 b) {
    return make_float4(a.x + b.x, a.y + b.y, a.z + b.z, a.w + b.w);
}
__device__ __forceinline__ float4 f4scale(float4 a, float s) {
    return make_float4(a.x * s, a.y * s, a.z * s, a.w * s);
}
__device__ __forceinline__ float4 f4zero() { return make_float4(0.f, 0.f, 0.f, 0.f); }

struct GroupSums {
    float4 c0, c1, c2, c3;   // pair2 sums
    float4 d0, d1;           // pair4 sums
    float4 e;                // pair8 sum
    int n0, n1, n2, n3, m0, m1, q;
};

// Load + mask + hierarchical-sum one pair8 group.
__device__ __forceinline__ GroupSums load_group(
    const float4* __restrict__ xb, const void* __restrict__ mask_raw,
    bool mask_is_byte, int b, int g)
{
    const int t0 = g * 8;
    int mi[8];
    if (mask_is_byte) {
        const uint8_t* mb = (const uint8_t*)mask_raw + (size_t)b * T + t0;
        const uint64_t mw = *reinterpret_cast<const uint64_t*>(mb);
        #pragma unroll
        for (int i = 0; i < 8; ++i) mi[i] = (int)((mw >> (8 * i)) & 1u);
    } else {
        const int4* mw = reinterpret_cast<const int4*>(
            (const int*)mask_raw + (size_t)b * T + t0);
        int4 a = mw[0], c = mw[1];
        mi[0] = (a.x != 0); mi[1] = (a.y != 0); mi[2] = (a.z != 0); mi[3] = (a.w != 0);
        mi[4] = (c.x != 0); mi[5] = (c.y != 0); mi[6] = (c.z != 0); mi[7] = (c.w != 0);
    }

    float4 v[8];
    const float4* xp = xb + (size_t)t0 * D4;
    #pragma unroll
    for (int i = 0; i < 8; ++i) v[i] = xp[(size_t)i * D4];
    #pragma unroll
    for (int i = 0; i < 8; ++i) if (!mi[i]) v[i] = f4zero();

    GroupSums s;
    s.c0 = f4add(v[0], v[1]); s.c1 = f4add(v[2], v[3]);
    s.c2 = f4add(v[4], v[5]); s.c3 = f4add(v[6], v[7]);
    s.n0 = mi[0] + mi[1]; s.n1 = mi[2] + mi[3];
    s.n2 = mi[4] + mi[5]; s.n3 = mi[6] + mi[7];
    s.d0 = f4add(s.c0, s.c1); s.d1 = f4add(s.c2, s.c3);
    s.m0 = s.n0 + s.n1; s.m1 = s.n2 + s.n3;
    s.e  = f4add(s.d0, s.d1);
    s.q  = s.m0 + s.m1;
    return s;
}

__global__ void __launch_bounds__(BLK, 14)
tpp_kernel(const float4* __restrict__ x,
           const void* __restrict__ mask_raw,
           float* __restrict__ out)
{
    const int blk   = blockIdx.x;               // 0..2047
    const int dhalf = blk % DSPLIT;             // adjacent CTAs share the tile
    const int tile  = blk / DSPLIT;             // 0..1023
    const int b     = tile / BLOCKS_PER_B;
    const int g0    = (tile % BLOCKS_PER_B) * GPB;
    const int d4    = dhalf * BLK + threadIdx.x;   // 0..127

    // ---- mask storage-layout detection (byte vs int32) ----
    __shared__ int s_is_byte;
    if (threadIdx.x < 32) {
        unsigned w = ((const unsigned*)mask_raw)[threadIdx.x];
        int bad = __any_sync(0xffffffffu, (w > 1u) ? 1 : 0);
        if (threadIdx.x == 0) s_is_byte = bad;
    }
    __syncthreads();
    const bool mask_is_byte = (s_is_byte != 0);

    const float4* xb = x + (size_t)b * T * D4 + d4;

    float4* const vis4  = (float4*)out;
    float4* const vis8  = vis4  + (size_t)B * S4  * D4;
    float4* const vis16 = vis8  + (size_t)B * S8  * D4;
    float*  const msk4  = out + (size_t)B * (S4 + S8 + S16) * D;
    float*  const msk8  = msk4 + B * S4;
    float*  const msk16 = msk8 + B * S8;

    const bool writeMsk = (threadIdx.x == 0) && (dhalf == 0);

    float4 prev_c3 = f4zero(), prev_d1 = f4zero(), prev_e = f4zero();
    int    prev_n3 = 0,        prev_m1 = 0,        prev_q = 0;

    #pragma unroll
    for (int k = 0; k < GPB; ++k) {
        const int g = g0 + k;
        const GroupSums s = load_group(xb, mask_raw, mask_is_byte, b, g);

        if (k > 0) {
            {   // win4 at 4g-1 (crosses group boundary)
                const int si = 4 * g - 1;
                const int cnt = prev_n3 + s.n0;
                __stcs(&vis4[(size_t)(b * S4 + si) * D4 + d4],
                       f4scale(f4add(prev_c3, s.c0), c_inv[cnt]));
                if (writeMsk) __stcs(&msk4[b * S4 + si], (cnt > 0) ? 1.0f : 0.0f);
            }
            {   // win8 at 2g-1
                const int h = 2 * g - 1;
                const int cnt = prev_m1 + s.m0;
                __stcs(&vis8[(size_t)(b * S8 + h) * D4 + d4],
                       f4scale(f4add(prev_d1, s.d0), c_inv[cnt]));
                if (writeMsk) __stcs(&msk8[b * S8 + h], (cnt > 0) ? 1.0f : 0.0f);
            }
            {   // win16 at g-1
                const int cnt = prev_q + s.q;
                __stcs(&vis16[(size_t)(b * S16 + (g - 1)) * D4 + d4],
                       f4scale(f4add(prev_e, s.e), c_inv[cnt]));
                if (writeMsk) __stcs(&msk16[b * S16 + (g - 1)], (cnt > 0) ? 1.0f : 0.0f);
            }
        }
        {   // in-tile outputs
            const int si = 4 * g;
            int cnt;
            cnt = s.n0 + s.n1;
            __stcs(&vis4[(size_t)(b * S4 + si    ) * D4 + d4],
                   f4scale(f4add(s.c0, s.c1), c_inv[cnt]));
            if (writeMsk) __stcs(&msk4[b * S4 + si    ], (cnt > 0) ? 1.0f : 0.0f);
            cnt = s.n1 + s.n2;
            __stcs(&vis4[(size_t)(b * S4 + si + 1) * D4 + d4],
                   f4scale(f4add(s.c1, s.c2), c_inv[cnt]));
            if (writeMsk) __stcs(&msk4[b * S4 + si + 1], (cnt > 0) ? 1.0f : 0.0f);
            cnt = s.n2 + s.n3;
            __stcs(&vis4[(size_t)(b * S4 + si + 2) * D4 + d4],
                   f4scale(f4add(s.c2, s.c3), c_inv[cnt]));
            if (writeMsk) __stcs(&msk4[b * S4 + si + 2], (cnt > 0) ? 1.0f : 0.0f);

            const int h = 2 * g;
            cnt = s.m0 + s.m1;
            __stcs(&vis8[(size_t)(b * S8 + h) * D4 + d4],
                   f4scale(f4add(s.d0, s.d1), c_inv[cnt]));
            if (writeMsk) __stcs(&msk8[b * S8 + h], (cnt > 0) ? 1.0f : 0.0f);
        }

        prev_c3 = s.c3; prev_d1 = s.d1; prev_e = s.e;
        prev_n3 = s.n3; prev_m1 = s.m1; prev_q = s.q;
    }

    // ---- halo epilogue: boundary windows into group gEnd (owned by this block) ----
    const int gEnd = g0 + GPB;
    if (gEnd < NGROUPS) {
        const GroupSums s = load_group(xb, mask_raw, mask_is_byte, b, gEnd);
        {   // win4 at 4*gEnd-1
            const int si = 4 * gEnd - 1;
            const int cnt = prev_n3 + s.n0;
            __stcs(&vis4[(size_t)(b * S4 + si) * D4 + d4],
                   f4scale(f4add(prev_c3, s.c0), c_inv[cnt]));
            if (writeMsk) __stcs(&msk4[b * S4 + si], (cnt > 0) ? 1.0f : 0.0f);
        }
        {   // win8 at 2*gEnd-1
            const int h = 2 * gEnd - 1;
            const int cnt = prev_m1 + s.m0;
            __stcs(&vis8[(size_t)(b * S8 + h) * D4 + d4],
                   f4scale(f4add(prev_d1, s.d0), c_inv[cnt]));
            if (writeMsk) __stcs(&msk8[b * S8 + h], (cnt > 0) ? 1.0f : 0.0f);
        }
        {   // win16 at gEnd-1
            const int cnt = prev_q + s.q;
            __stcs(&vis16[(size_t)(b * S16 + (gEnd - 1)) * D4 + d4],
                   f4scale(f4add(prev_e, s.e), c_inv[cnt]));
            if (writeMsk) __stcs(&msk16[b * S16 + (gEnd - 1)], (cnt > 0) ? 1.0f : 0.0f);
        }
    }
}

extern "C" void kernel_launch(void* const* d_in, const int* in_sizes, int n_in,
                              void* d_out, int out_size)
{
    const float4* x    = (const float4*)d_in[0];
    const void*   mask = (const void*)d_in[1];
    float*        out  = (float*)d_out;

    tpp_kernel<<<B * BLOCKS_PER_B * DSPLIT, BLK>>>(x, mask, out);
}

// round 9
// speedup vs baseline: 1.7348x; 1.0135x over previous
#include <cuda_runtime.h>
#include <cstdint>

// TemporalPyramidPooling: overlapping masked window means at w=4/8/16, stride w/2.
// Hierarchical non-overlapping pair sums; float4-vectorized over D.
// R9: same as R8 but evict_last expressed via createpolicy + ld.global.nc.L2::cache_hint
//     (ptxas on sm_103a rejects the immediate .L2::evict_last modifier on v4.f32).
//     DSPLIT=4 (1-warp CTAs, 4096 CTAs, warp-vote mask detect) at GPB=4 (25% halo);
//     outputs stream out evict-first via __stcs.
//
//   x    [B=8, T=4096, D=512] f32
//   mask [B, T]  (bool; stored as 1-byte or int32 0/1 -- detected at runtime)
// Outputs concatenated f32:
//   vis4 [B,2047,D], vis8 [B,1023,D], vis16 [B,511,D],
//   msk4 [B,2047],   msk8 [B,1023],   msk16 [B,511]

namespace {
constexpr int B   = 8;
constexpr int T   = 4096;
constexpr int D   = 512;
constexpr int D4  = D / 4;                  // 128 float4 lanes
constexpr int S4  = 2047;
constexpr int S8  = 1023;
constexpr int S16 = 511;
constexpr int NGROUPS = T / 8;              // 512 pair8 groups per batch
constexpr int GPB = 4;                      // groups per block (tile = 32 t)
constexpr int BLOCKS_PER_B = NGROUPS / GPB; // 128
constexpr int DSPLIT = 4;                   // CTAs per (b, gtile) along D
constexpr int BLK = D4 / DSPLIT;            // 32 threads = 1 warp
}

// 1/max(count,1e-6) for counts 0..16 (count==0 -> sum==0, product 0 matches ref)
__constant__ float c_inv[17] = {
    1e6f, 1.0f, 0.5f, 1.0f/3.0f, 0.25f, 0.2f, 1.0f/6.0f, 1.0f/7.0f,
    0.125f, 1.0f/9.0f, 0.1f, 1.0f/11.0f, 1.0f/12.0f, 1.0f/13.0f,
    1.0f/14.0f, 1.0f/15.0f, 0.0625f
};

__device__ __forceinline__ float4 f4add(float4 a, float4 b) {
    return make_float4(a.x + b.x, a.y + b.y, a.z + b.z, a.w + b.w);
}
__device__ __forceinline__ float4 f4scale(float4 a, float s) {
    return make_float4(a.x * s, a.y * s, a.z * s, a.w * s);
}
__device__ __forceinline__ float4 f4zero() { return make_float4(0.f, 0.f, 0.f, 0.f); }

// L2 evict-last access policy (whole-allocation fractional policy).
__device__ __forceinline__ uint64_t make_evict_last_policy() {
    uint64_t pol;
    asm("createpolicy.fractional.L2::evict_last.b64 %0, 1.0;" : "=l"(pol));
    return pol;
}

// Read-only x load with L2 evict-last priority via cache_hint.
__device__ __forceinline__ float4 ldg_el(const float4* p, uint64_t pol) {
    float4 r;
    asm("ld.global.nc.L2::cache_hint.v4.f32 {%0,%1,%2,%3}, [%4], %5;"
        : "=f"(r.x), "=f"(r.y), "=f"(r.z), "=f"(r.w) : "l"(p), "l"(pol));
    return r;
}

struct GroupSums {
    float4 c0, c1, c2, c3;   // pair2 sums
    float4 d0, d1;           // pair4 sums
    float4 e;                // pair8 sum
    int n0, n1, n2, n3, m0, m1, q;
};

// Load + mask + hierarchical-sum one pair8 group.
__device__ __forceinline__ GroupSums load_group(
    const float4* __restrict__ xb, const void* __restrict__ mask_raw,
    bool mask_is_byte, int b, int g, uint64_t pol)
{
    const int t0 = g * 8;
    int mi[8];
    if (mask_is_byte) {
        const uint8_t* mb = (const uint8_t*)mask_raw + (size_t)b * T + t0;
        const uint64_t mw = *reinterpret_cast<const uint64_t*>(mb);
        #pragma unroll
        for (int i = 0; i < 8; ++i) mi[i] = (int)((mw >> (8 * i)) & 1u);
    } else {
        const int4* mw = reinterpret_cast<const int4*>(
            (const int*)mask_raw + (size_t)b * T + t0);
        int4 a = mw[0], c = mw[1];
        mi[0] = (a.x != 0); mi[1] = (a.y != 0); mi[2] = (a.z != 0); mi[3] = (a.w != 0);
        mi[4] = (c.x != 0); mi[5] = (c.y != 0); mi[6] = (c.z != 0); mi[7] = (c.w != 0);
    }

    float4 v[8];
    const float4* xp = xb + (size_t)t0 * D4;
    #pragma unroll
    for (int i = 0; i < 8; ++i) v[i] = ldg_el(xp + (size_t)i * D4, pol);
    #pragma unroll
    for (int i = 0; i < 8; ++i) if (!mi[i]) v[i] = f4zero();

    GroupSums s;
    s.c0 = f4add(v[0], v[1]); s.c1 = f4add(v[2], v[3]);
    s.c2 = f4add(v[4], v[5]); s.c3 = f4add(v[6], v[7]);
    s.n0 = mi[0] + mi[1]; s.n1 = mi[2] + mi[3];
    s.n2 = mi[4] + mi[5]; s.n3 = mi[6] + mi[7];
    s.d0 = f4add(s.c0, s.c1); s.d1 = f4add(s.c2, s.c3);
    s.m0 = s.n0 + s.n1; s.m1 = s.n2 + s.n3;
    s.e  = f4add(s.d0, s.d1);
    s.q  = s.m0 + s.m1;
    return s;
}

__global__ void __launch_bounds__(BLK)
tpp_kernel(const float4* __restrict__ x,
           const void* __restrict__ mask_raw,
           float* __restrict__ out)
{
    const int blk   = blockIdx.x;               // 0..4095
    const int dpart = blk % DSPLIT;             // adjacent CTAs share the tile
    const int tile  = blk / DSPLIT;             // 0..1023
    const int b     = tile / BLOCKS_PER_B;
    const int g0    = (tile % BLOCKS_PER_B) * GPB;
    const int d4    = dpart * BLK + threadIdx.x;   // 0..127

    const uint64_t pol = make_evict_last_policy();

    // ---- mask storage-layout detection (byte vs int32), warp-uniform ----
    unsigned w = ((const unsigned*)mask_raw)[threadIdx.x];
    const bool mask_is_byte = __any_sync(0xffffffffu, w > 1u);

    const float4* xb = x + (size_t)b * T * D4 + d4;

    float4* const vis4  = (float4*)out;
    float4* const vis8  = vis4  + (size_t)B * S4  * D4;
    float4* const vis16 = vis8  + (size_t)B * S8  * D4;
    float*  const msk4  = out + (size_t)B * (S4 + S8 + S16) * D;
    float*  const msk8  = msk4 + B * S4;
    float*  const msk16 = msk8 + B * S8;

    const bool writeMsk = (threadIdx.x == 0) && (dpart == 0);

    float4 prev_c3 = f4zero(), prev_d1 = f4zero(), prev_e = f4zero();
    int    prev_n3 = 0,        prev_m1 = 0,        prev_q = 0;

    #pragma unroll
    for (int k = 0; k < GPB; ++k) {
        const int g = g0 + k;
        const GroupSums s = load_group(xb, mask_raw, mask_is_byte, b, g, pol);

        if (k > 0) {
            {   // win4 at 4g-1 (crosses group boundary)
                const int si = 4 * g - 1;
                const int cnt = prev_n3 + s.n0;
                __stcs(&vis4[(size_t)(b * S4 + si) * D4 + d4],
                       f4scale(f4add(prev_c3, s.c0), c_inv[cnt]));
                if (writeMsk) __stcs(&msk4[b * S4 + si], (cnt > 0) ? 1.0f : 0.0f);
            }
            {   // win8 at 2g-1
                const int h = 2 * g - 1;
                const int cnt = prev_m1 + s.m0;
                __stcs(&vis8[(size_t)(b * S8 + h) * D4 + d4],
                       f4scale(f4add(prev_d1, s.d0), c_inv[cnt]));
                if (writeMsk) __stcs(&msk8[b * S8 + h], (cnt > 0) ? 1.0f : 0.0f);
            }
            {   // win16 at g-1
                const int cnt = prev_q + s.q;
                __stcs(&vis16[(size_t)(b * S16 + (g - 1)) * D4 + d4],
                       f4scale(f4add(prev_e, s.e), c_inv[cnt]));
                if (writeMsk) __stcs(&msk16[b * S16 + (g - 1)], (cnt > 0) ? 1.0f : 0.0f);
            }
        }
        {   // in-tile outputs
            const int si = 4 * g;
            int cnt;
            cnt = s.n0 + s.n1;
            __stcs(&vis4[(size_t)(b * S4 + si    ) * D4 + d4],
                   f4scale(f4add(s.c0, s.c1), c_inv[cnt]));
            if (writeMsk) __stcs(&msk4[b * S4 + si    ], (cnt > 0) ? 1.0f : 0.0f);
            cnt = s.n1 + s.n2;
            __stcs(&vis4[(size_t)(b * S4 + si + 1) * D4 + d4],
                   f4scale(f4add(s.c1, s.c2), c_inv[cnt]));
            if (writeMsk) __stcs(&msk4[b * S4 + si + 1], (cnt > 0) ? 1.0f : 0.0f);
            cnt = s.n2 + s.n3;
            __stcs(&vis4[(size_t)(b * S4 + si + 2) * D4 + d4],
                   f4scale(f4add(s.c2, s.c3), c_inv[cnt]));
            if (writeMsk) __stcs(&msk4[b * S4 + si + 2], (cnt > 0) ? 1.0f : 0.0f);

            const int h = 2 * g;
            cnt = s.m0 + s.m1;
            __stcs(&vis8[(size_t)(b * S8 + h) * D4 + d4],
                   f4scale(f4add(s.d0, s.d1), c_inv[cnt]));
            if (writeMsk) __stcs(&msk8[b * S8 + h], (cnt > 0) ? 1.0f : 0.0f);
        }

        prev_c3 = s.c3; prev_d1 = s.d1; prev_e = s.e;
        prev_n3 = s.n3; prev_m1 = s.m1; prev_q = s.q;
    }

    // ---- halo epilogue: boundary windows into group gEnd (owned by this block) ----
    const int gEnd = g0 + GPB;
    if (gEnd < NGROUPS) {
        const GroupSums s = load_group(xb, mask_raw, mask_is_byte, b, gEnd, pol);
        {   // win4 at 4*gEnd-1
            const int si = 4 * gEnd - 1;
            const int cnt = prev_n3 + s.n0;
            __stcs(&vis4[(size_t)(b * S4 + si) * D4 + d4],
                   f4scale(f4add(prev_c3, s.c0), c_inv[cnt]));
            if (writeMsk) __stcs(&msk4[b * S4 + si], (cnt > 0) ? 1.0f : 0.0f);
        }
        {   // win8 at 2*gEnd-1
            const int h = 2 * gEnd - 1;
            const int cnt = prev_m1 + s.m0;
            __stcs(&vis8[(size_t)(b * S8 + h) * D4 + d4],
                   f4scale(f4add(prev_d1, s.d0), c_inv[cnt]));
            if (writeMsk) __stcs(&msk8[b * S8 + h], (cnt > 0) ? 1.0f : 0.0f);
        }
        {   // win16 at gEnd-1
            const int cnt = prev_q + s.q;
            __stcs(&vis16[(size_t)(b * S16 + (gEnd - 1)) * D4 + d4],
                   f4scale(f4add(prev_e, s.e), c_inv[cnt]));
            if (writeMsk) __stcs(&msk16[b * S16 + (gEnd - 1)], (cnt > 0) ? 1.0f : 0.0f);
        }
    }
}

extern "C" void kernel_launch(void* const* d_in, const int* in_sizes, int n_in,
                              void* d_out, int out_size)
{
    const float4* x    = (const float4*)d_in[0];
    const void*   mask = (const void*)d_in[1];
    float*        out  = (float*)d_out;

    tpp_kernel<<<B * BLOCKS_PER_B * DSPLIT, BLK>>>(x, mask, out);
}